// round 6
// baseline (speedup 1.0000x reference)
#include <cuda_runtime.h>

// IF (integrate-and-fire) scan. x: (B=32, T=8, CHW=200704) fp32.
// FINAL: HBM-roofline streaming kernel. 411MB moved in ~57.7us = 7.1TB/s
// effective (~89% of 8TB/s spec). R1-R5 showed structure-invariant plateau:
// plain/ldcs/stcs, 1x/2x unroll, persistent vs exact grid all within noise.
// This round: R3 config (plain loads + evict-first stores) with a 2D grid
// (y = batch) eliminating the 64-bit div/mod and the tail predicate.
//   gridDim = (196, 32): 196*256 = 50176 = CHW4 exactly.

#define T_STEPS 8
#define BATCH 32
#define CHW4 50176              // (64*56*56)/4 float4 per timestep-slice
#define VTH 1.0f

__global__ void __launch_bounds__(256) if_scan_kernel(
    const float4* __restrict__ x, float4* __restrict__ out)
{
    const int p = blockIdx.x * 256 + threadIdx.x;     // 0 .. CHW4-1, exact
    const int b = blockIdx.y;                          // batch index
    const long long base = (long long)b * (T_STEPS * CHW4) + p;

    // Front-batch all 8 loads (independent of scan state) -> MLP=8
    float4 xt[T_STEPS];
#pragma unroll
    for (int t = 0; t < T_STEPS; t++)
        xt[t] = x[base + t * CHW4];

    float mx = 0.f, my = 0.f, mz = 0.f, mw = 0.f;
#pragma unroll
    for (int t = 0; t < T_STEPS; t++) {
        mx += xt[t].x; my += xt[t].y; mz += xt[t].z; mw += xt[t].w;
        float4 s;
        s.x = (mx > VTH) ? 1.0f : 0.0f;
        s.y = (my > VTH) ? 1.0f : 0.0f;
        s.z = (mz > VTH) ? 1.0f : 0.0f;
        s.w = (mw > VTH) ? 1.0f : 0.0f;
        mx = (mx > VTH) ? 0.0f : mx;
        my = (my > VTH) ? 0.0f : my;
        mz = (mz > VTH) ? 0.0f : mz;
        mw = (mw > VTH) ? 0.0f : mw;
        // Evict-first: output is write-once, never re-read.
        __stcs(out + base + t * CHW4, s);
    }
}

extern "C" void kernel_launch(void* const* d_in, const int* in_sizes, int n_in,
                              void* d_out, int out_size)
{
    const float4* x = (const float4*)d_in[0];
    float4* out = (float4*)d_out;
    dim3 grid(CHW4 / 256, BATCH, 1);   // (196, 32)
    if_scan_kernel<<<grid, 256>>>(x, out);
}

// round 7
// speedup vs baseline: 1.0165x; 1.0165x over previous
#include <cuda_runtime.h>

// IF (integrate-and-fire) scan. x: (B=32, T=8, CHW=200704) fp32.
// FINAL: HBM-roofline streaming kernel. 411MB in ~57us = 7.2TB/s effective
// (both directions). R1-R6 evidence: plateau is structure-invariant
// (plain/ldcs/stcs, 1x/2x unroll, persistent vs exact, 1D vs 2D grid all
// within ~1us kernel time); best config is 2D-grid + plain loads +
// evict-first stores (R6: 56.96us kernel, DRAM 78.7%).
// R7: block=512 (grid 98x32) — same per-thread pattern, half the CTAs,
// same 75% theoretical occupancy (3 CTAs x 16 warps/SM).

#define T_STEPS 8
#define BATCH 32
#define CHW4 50176              // (64*56*56)/4 float4 per timestep-slice
#define VTH 1.0f

__global__ void __launch_bounds__(512) if_scan_kernel(
    const float4* __restrict__ x, float4* __restrict__ out)
{
    const int p = blockIdx.x * 512 + threadIdx.x;     // 0 .. CHW4-1, exact
    const int b = blockIdx.y;                          // batch index
    const long long base = (long long)b * (T_STEPS * CHW4) + p;

    // Front-batch all 8 loads (independent of scan state) -> MLP=8
    float4 xt[T_STEPS];
#pragma unroll
    for (int t = 0; t < T_STEPS; t++)
        xt[t] = x[base + t * CHW4];

    float mx = 0.f, my = 0.f, mz = 0.f, mw = 0.f;
#pragma unroll
    for (int t = 0; t < T_STEPS; t++) {
        mx += xt[t].x; my += xt[t].y; mz += xt[t].z; mw += xt[t].w;
        float4 s;
        s.x = (mx > VTH) ? 1.0f : 0.0f;
        s.y = (my > VTH) ? 1.0f : 0.0f;
        s.z = (mz > VTH) ? 1.0f : 0.0f;
        s.w = (mw > VTH) ? 1.0f : 0.0f;
        mx = (mx > VTH) ? 0.0f : mx;
        my = (my > VTH) ? 0.0f : my;
        mz = (mz > VTH) ? 0.0f : mz;
        mw = (mw > VTH) ? 0.0f : mw;
        // Evict-first: output is write-once, never re-read.
        __stcs(out + base + t * CHW4, s);
    }
}

extern "C" void kernel_launch(void* const* d_in, const int* in_sizes, int n_in,
                              void* d_out, int out_size)
{
    const float4* x = (const float4*)d_in[0];
    float4* out = (float4*)d_out;
    dim3 grid(CHW4 / 512, BATCH, 1);   // (98, 32)
    if_scan_kernel<<<grid, 512>>>(x, out);
}

// round 8
// speedup vs baseline: 1.0170x; 1.0005x over previous
#include <cuda_runtime.h>

// IF (integrate-and-fire) scan. x: (B=32, T=8, CHW=200704) fp32.
// HBM-roofline streaming kernel (~7.2TB/s effective bidirectional).
// R6 config (block 256, 2D grid, plain loads, evict-first stores) is the
// best measured: 56.96us kernel, DRAM 78.7%. R8 variant: fully phase-
// separated load burst -> compute -> store burst, so the LSU issues 8
// back-to-back loads then 8 back-to-back stores (fewer R/W direction
// switches per thread at the memory controller).

#define T_STEPS 8
#define BATCH 32
#define CHW4 50176              // (64*56*56)/4 float4 per timestep-slice
#define VTH 1.0f

__global__ void __launch_bounds__(256) if_scan_kernel(
    const float4* __restrict__ x, float4* __restrict__ out)
{
    const int p = blockIdx.x * 256 + threadIdx.x;     // 0 .. CHW4-1, exact
    const int b = blockIdx.y;                          // batch index
    const long long base = (long long)b * (T_STEPS * CHW4) + p;

    // Phase 1: load burst (8 independent LDG.128, MLP=8)
    float4 xt[T_STEPS];
#pragma unroll
    for (int t = 0; t < T_STEPS; t++)
        xt[t] = x[base + t * CHW4];

    // Phase 2: scan entirely in registers
    float4 sp[T_STEPS];
    float mx = 0.f, my = 0.f, mz = 0.f, mw = 0.f;
#pragma unroll
    for (int t = 0; t < T_STEPS; t++) {
        mx += xt[t].x; my += xt[t].y; mz += xt[t].z; mw += xt[t].w;
        sp[t].x = (mx > VTH) ? 1.0f : 0.0f;
        sp[t].y = (my > VTH) ? 1.0f : 0.0f;
        sp[t].z = (mz > VTH) ? 1.0f : 0.0f;
        sp[t].w = (mw > VTH) ? 1.0f : 0.0f;
        mx = (mx > VTH) ? 0.0f : mx;
        my = (my > VTH) ? 0.0f : my;
        mz = (mz > VTH) ? 0.0f : mz;
        mw = (mw > VTH) ? 0.0f : mw;
    }

    // Phase 3: store burst (8 back-to-back STG.128, evict-first)
#pragma unroll
    for (int t = 0; t < T_STEPS; t++)
        __stcs(out + base + t * CHW4, sp[t]);
}

extern "C" void kernel_launch(void* const* d_in, const int* in_sizes, int n_in,
                              void* d_out, int out_size)
{
    const float4* x = (const float4*)d_in[0];
    float4* out = (float4*)d_out;
    dim3 grid(CHW4 / 256, BATCH, 1);   // (196, 32)
    if_scan_kernel<<<grid, 256>>>(x, out);
}